// round 3
// baseline (speedup 1.0000x reference)
#include <cuda_runtime.h>
#include <math.h>

#define BB 16
#define NPIX 245760          // 384*640
#define NPIX4 (NPIX/4)
#define N2  491520           // 2*NPIX

// ---------------- scratch (static device memory; no runtime allocs) ----------------
__device__ double g_sums[BB][5];                      // a00,a01,a11,b0,b1
__device__ int    g_cntm[BB];                         // masked gt count (= n)
__device__ int    g_cnt[BB];                          // static-pixel count
__device__ float  g_rr[BB];
__device__ float  g_loss[32];
__device__ unsigned int g_l0_pref[64], g_l0_rank[64];
__device__ unsigned int g_l1_pref[64], g_l1_rank[64];
__device__ unsigned int g_hist0[BB][2048];
__device__ unsigned int g_hist1[64][2048];
__device__ unsigned int g_hist2[64][1024];
__device__ unsigned int g_keys[(size_t)BB * N2];      // compacted masked gt keys
__device__ unsigned int g_rd_keys[(size_t)BB * NPIX];
__device__ unsigned int g_ra_keys[(size_t)BB * NPIX];
__device__ float  g_dp [(size_t)BB * NPIX];
__device__ float  g_dgt[(size_t)BB * NPIX];
__device__ unsigned char g_m12[(size_t)BB * NPIX4];

// ---------------- helpers ----------------
__device__ __forceinline__ unsigned int fkey(float x) {
    unsigned int u = __float_as_uint(x);
    return (u & 0x80000000u) ? ~u : (u | 0x80000000u);
}
__device__ __forceinline__ float kinv(unsigned int k) {
    unsigned int u = (k & 0x80000000u) ? (k & 0x7fffffffu) : ~k;
    return __uint_as_float(u);
}
__device__ __forceinline__ float hubf(float v) {
    return (v <= 0.03f) ? (0.5f * (v * v)) / 0.03f : (v - 0.015f);
}

// 256-thread block exclusive scan of chunk sums over sh[0..nb). Ends with sync.
__device__ __forceinline__ void block_exscan_chunks(const unsigned int* sh,
                                                    unsigned int* sP, int chunk) {
    int tid = threadIdx.x;
    unsigned s = 0;
#pragma unroll 4
    for (int j = 0; j < chunk; j++) s += sh[tid * chunk + j];
    int lane = tid & 31, wp = tid >> 5;
    unsigned v = s;
#pragma unroll
    for (int o = 1; o < 32; o <<= 1) {
        unsigned n = __shfl_up_sync(0xffffffffu, v, o);
        if (lane >= o) v += n;
    }
    __shared__ unsigned wtot[8];
    if (lane == 31) wtot[wp] = v;
    __syncthreads();
    unsigned wo = 0;
    for (int w = 0; w < wp; w++) wo += wtot[w];
    unsigned excl = wo + v - s;
    sP[tid] = excl;
    if (tid == 255) sP[256] = excl + s;
    __syncthreads();
}

__device__ __forceinline__ void resolve_one(const unsigned int* sh, const unsigned int* sP,
                                            int chunk, int nb, unsigned rank,
                                            unsigned* bin_out, unsigned* rem_out) {
    int lo = 0, hi = 255;
    while (lo < hi) {
        int mid = (lo + hi + 1) >> 1;
        if (sP[mid] <= rank) lo = mid; else hi = mid - 1;
    }
    unsigned cum = sP[lo];
    int bin = lo * chunk;
    int end = bin + chunk;
    if (end > nb) end = nb;
    while (bin + 1 < end && cum + sh[bin] <= rank) { cum += sh[bin]; bin++; }
    *bin_out = (unsigned)bin;
    *rem_out = rank - cum;
}

__device__ __forceinline__ void ranks_for_n(int n, unsigned* r) {
    int nm1 = (n > 1) ? (n - 1) : 0;
    float pos05 = 0.05f * (float)nm1;
    float pos95 = 0.95f * (float)nm1;
    r[0] = (unsigned)floorf(pos05);
    r[1] = (unsigned)ceilf(pos05);
    r[2] = (unsigned)floorf(pos95);
    r[3] = (unsigned)ceilf(pos95);
}

// ---------------- kernels ----------------
__global__ void k_zero() {
    int i = blockIdx.x * blockDim.x + threadIdx.x;
    int stride = gridDim.x * blockDim.x;
    for (int x = i; x < BB * 2048; x += stride) ((unsigned int*)g_hist0)[x] = 0u;
    for (int x = i; x < 64 * 2048; x += stride) ((unsigned int*)g_hist1)[x] = 0u;
    for (int x = i; x < 64 * 1024; x += stride) ((unsigned int*)g_hist2)[x] = 0u;
    if (i < BB) {
        for (int j = 0; j < 5; j++) g_sums[i][j] = 0.0;
        g_cntm[i] = 0;
        g_cnt[i] = 0;
    }
}

// Pass 1: moments + compacted gt keys + hist L0 + dp/dgt/m12 precompute
__global__ void k_stats(const float* __restrict__ pred, const float* __restrict__ gt,
                        const float* __restrict__ mask) {
    __shared__ unsigned int hh[2048];
    int b = blockIdx.y;
    for (int i = threadIdx.x; i < 2048; i += blockDim.x) hh[i] = 0u;
    __syncthreads();
    const float4* p0 = (const float4*)(pred + (size_t)b * N2);
    const float4* p1 = (const float4*)(pred + (size_t)b * N2 + NPIX);
    const float4* g0 = (const float4*)(gt   + (size_t)b * N2);
    const float4* g1 = (const float4*)(gt   + (size_t)b * N2 + NPIX);
    const float4* m0 = (const float4*)(mask + (size_t)b * N2);
    const float4* m1 = (const float4*)(mask + (size_t)b * N2 + NPIX);
    float4* dp4  = (float4*)(g_dp  + (size_t)b * NPIX);
    float4* dg4  = (float4*)(g_dgt + (size_t)b * NPIX);
    unsigned char* mm = g_m12 + (size_t)b * NPIX4;
    unsigned int* keys = g_keys + (size_t)b * N2;
    float a00 = 0.f, a01 = 0.f, a11 = 0.f, bb0 = 0.f, bb1 = 0.f;
    int lane = threadIdx.x & 31;
    unsigned lmask = (1u << lane) - 1u;
    int tot_threads = gridDim.x * blockDim.x;
    for (int i = blockIdx.x * blockDim.x + threadIdx.x; i < NPIX4; i += tot_threads) {
        float4 P0 = p0[i], P1 = p1[i], G0 = g0[i], G1 = g1[i], M0 = m0[i], M1 = m1[i];
        float4 dpv, dgv;
        bool act[8]; unsigned kv[8];
        unsigned mbyte = 0;
#define DO(c, idx, bit) { bool a0 = M0.c > 0.5f, a1 = M1.c > 0.5f; \
        if (a0) { a00 += P0.c * P0.c; a01 += P0.c; a11 += 1.f; bb0 += P0.c * G0.c; bb1 += G0.c; } \
        if (a1) { a00 += P1.c * P1.c; a01 += P1.c; a11 += 1.f; bb0 += P1.c * G1.c; bb1 += G1.c; } \
        act[idx] = a0; kv[idx] = fkey(G0.c); act[idx + 4] = a1; kv[idx + 4] = fkey(G1.c); \
        if (a0 && a1) mbyte |= (1u << bit); \
        dpv.c = P1.c - P0.c; dgv.c = G1.c - G0.c; }
        DO(x, 0, 0) DO(y, 1, 1) DO(z, 2, 2) DO(w, 3, 3)
#undef DO
        unsigned bals[8]; int tot = 0;
#pragma unroll
        for (int s = 0; s < 8; s++) { bals[s] = __ballot_sync(0xffffffffu, act[s]); tot += __popc(bals[s]); }
        unsigned base = 0;
        if (lane == 0) base = (unsigned)atomicAdd(&g_cntm[b], tot);
        base = __shfl_sync(0xffffffffu, base, 0);
        unsigned off = base;
#pragma unroll
        for (int s = 0; s < 8; s++) {
            if (act[s]) {
                unsigned pos = off + __popc(bals[s] & lmask);
                keys[pos] = kv[s];
                atomicAdd(&hh[kv[s] >> 21], 1u);
            }
            off += __popc(bals[s]);
        }
        dp4[i] = dpv; dg4[i] = dgv; mm[i] = (unsigned char)mbyte;
    }
    double d0 = a00, d1 = a01, d2 = a11, d3 = bb0, d4 = bb1;
    for (int off = 16; off > 0; off >>= 1) {
        d0 += __shfl_down_sync(0xffffffffu, d0, off);
        d1 += __shfl_down_sync(0xffffffffu, d1, off);
        d2 += __shfl_down_sync(0xffffffffu, d2, off);
        d3 += __shfl_down_sync(0xffffffffu, d3, off);
        d4 += __shfl_down_sync(0xffffffffu, d4, off);
    }
    __shared__ double shd[8][5];
    int wp = threadIdx.x >> 5;
    if (lane == 0) { shd[wp][0] = d0; shd[wp][1] = d1; shd[wp][2] = d2; shd[wp][3] = d3; shd[wp][4] = d4; }
    __syncthreads();
    if (threadIdx.x == 0) {
        double s0 = 0, s1 = 0, s2 = 0, s3 = 0, s4 = 0;
        for (int w = 0; w < 8; w++) { s0 += shd[w][0]; s1 += shd[w][1]; s2 += shd[w][2]; s3 += shd[w][3]; s4 += shd[w][4]; }
        atomicAdd(&g_sums[b][0], s0); atomicAdd(&g_sums[b][1], s1);
        atomicAdd(&g_sums[b][2], s2); atomicAdd(&g_sums[b][3], s3);
        atomicAdd(&g_sums[b][4], s4);
    }
    unsigned int* gh = g_hist0[b];
    for (int i = threadIdx.x; i < 2048; i += blockDim.x) {
        unsigned v = hh[i];
        if (v) atomicAdd(&gh[i], v);
    }
}

// Pass 2: resolve L0 per-block (redundant), histogram level-1
__global__ void k_hist1() {
    __shared__ unsigned int sh[2048];
    __shared__ unsigned int sP[257];
    __shared__ unsigned int spref[4], srank[4];
    __shared__ unsigned int h4[4][2048];
    int b = blockIdx.y, tid = threadIdx.x;
    int n = g_cntm[b];
    for (int i = tid; i < 2048; i += 256) sh[i] = g_hist0[b][i];
    __syncthreads();
    block_exscan_chunks(sh, sP, 8);
    if (tid < 4) {
        unsigned rk[4]; ranks_for_n(n, rk);
        unsigned bin, rem;
        resolve_one(sh, sP, 8, 2048, rk[tid], &bin, &rem);
        spref[tid] = bin; srank[tid] = rem;
        g_l0_pref[b * 4 + tid] = bin; g_l0_rank[b * 4 + tid] = rem;  // same value from every block
    }
    __syncthreads();
    for (int i = tid; i < 4 * 2048; i += 256) ((unsigned int*)h4)[i] = 0u;
    __syncthreads();
    unsigned p0 = spref[0], p1 = spref[1], p2 = spref[2], p3 = spref[3];
    const unsigned int* keys = g_keys + (size_t)b * N2;
    for (int i = blockIdx.x * blockDim.x + tid; i < n; i += gridDim.x * blockDim.x) {
        unsigned key = keys[i];
        unsigned hi = key >> 21, bin = (key >> 10) & 2047u;
        if (hi == p0) atomicAdd(&h4[0][bin], 1u);
        if (hi == p1) atomicAdd(&h4[1][bin], 1u);
        if (hi == p2) atomicAdd(&h4[2][bin], 1u);
        if (hi == p3) atomicAdd(&h4[3][bin], 1u);
    }
    __syncthreads();
    for (int q = 0; q < 4; q++)
        for (int i = tid; i < 2048; i += 256) {
            unsigned v = h4[q][i];
            if (v) atomicAdd(&g_hist1[b * 4 + q][i], v);
        }
}

// Pass 3: resolve L1 per-block (redundant), histogram level-2
__global__ void k_hist2() {
    __shared__ unsigned int sh[2048];
    __shared__ unsigned int sP[257];
    __shared__ unsigned int spref[4], srank[4];
    __shared__ unsigned int h4[4][1024];
    int b = blockIdx.y, tid = threadIdx.x;
    int n = g_cntm[b];
    for (int q = 0; q < 4; q++) {
        for (int i = tid; i < 2048; i += 256) sh[i] = g_hist1[b * 4 + q][i];
        __syncthreads();
        block_exscan_chunks(sh, sP, 8);
        if (tid == 0) {
            unsigned bin, rem;
            resolve_one(sh, sP, 8, 2048, g_l0_rank[b * 4 + q], &bin, &rem);
            spref[q] = g_l0_pref[b * 4 + q] * 2048u + bin;
            srank[q] = rem;
            g_l1_pref[b * 4 + q] = spref[q]; g_l1_rank[b * 4 + q] = rem;
        }
        __syncthreads();
    }
    for (int i = tid; i < 4 * 1024; i += 256) ((unsigned int*)h4)[i] = 0u;
    __syncthreads();
    unsigned p0 = spref[0], p1 = spref[1], p2 = spref[2], p3 = spref[3];
    const unsigned int* keys = g_keys + (size_t)b * N2;
    for (int i = blockIdx.x * blockDim.x + tid; i < n; i += gridDim.x * blockDim.x) {
        unsigned key = keys[i];
        unsigned hi = key >> 10, bin = key & 1023u;
        if (hi == p0) atomicAdd(&h4[0][bin], 1u);
        if (hi == p1) atomicAdd(&h4[1][bin], 1u);
        if (hi == p2) atomicAdd(&h4[2][bin], 1u);
        if (hi == p3) atomicAdd(&h4[3][bin], 1u);
    }
    __syncthreads();
    for (int q = 0; q < 4; q++)
        for (int i = tid; i < 1024; i += 256) {
            unsigned v = h4[q][i];
            if (v) atomicAdd(&g_hist2[b * 4 + q][i], v);
        }
}

// Pass 4: resolve L2 + rr/th/scale + s,t per-block (redundant),
// curr_grad output + static residual compaction.
__global__ void k_compact(const float* __restrict__ prev, float* __restrict__ out) {
    __shared__ unsigned int sh[1024];
    __shared__ unsigned int sP[257];
    __shared__ unsigned int qkey[4];
    __shared__ float sh_s, sh_t, sh_th, sh_sc, sh_rr;
    int b = blockIdx.y, tid = threadIdx.x;
    for (int q = 0; q < 4; q++) {
        for (int i = tid; i < 1024; i += 256) sh[i] = g_hist2[b * 4 + q][i];
        __syncthreads();
        block_exscan_chunks(sh, sP, 4);
        if (tid == 0) {
            unsigned bin, rem;
            resolve_one(sh, sP, 4, 1024, g_l1_rank[b * 4 + q], &bin, &rem);
            qkey[q] = g_l1_pref[b * 4 + q] * 1024u + bin;
        }
        __syncthreads();
    }
    if (tid == 0) {
        double a00 = g_sums[b][0], a01 = g_sums[b][1], a11 = g_sums[b][2];
        double bb0 = g_sums[b][3], bb1 = g_sums[b][4];
        double det = a00 * a11 - a01 * a01;
        float s = 0.f, t = 0.f;
        if (det != 0.0) {
            double id = 1.0 / (det + 1e-6);
            s = (float)((a11 * bb0 - a01 * bb1) * id);
            t = (float)((-a01 * bb0 + a00 * bb1) * id);
        }
        int n = g_cntm[b];
        float rr = 1.0f;
        if (n > 0) {
            float v0 = kinv(qkey[0]), v1 = kinv(qkey[1]);
            float v2 = kinv(qkey[2]), v3 = kinv(qkey[3]);
            int nm1 = (n > 1) ? (n - 1) : 0;
            float pos05 = 0.05f * (float)nm1, pos95 = 0.95f * (float)nm1;
            float lo = v0 + (v1 - v0) * (pos05 - floorf(pos05));
            float hi = v2 + (v3 - v2) * (pos95 - floorf(pos95));
            bool valid = isfinite(lo) && isfinite(hi) && (hi - lo > 0.f) &&
                         (fabsf(lo) < 1e30f) && (fabsf(hi) < 1e30f);
            rr = valid ? fmaxf(hi - lo, 1e-6f) : 1.0f;
        }
        sh_s = s; sh_t = t; sh_rr = rr;
        sh_sc = fmaxf(rr, 1e-6f); sh_th = 0.01f * rr;
        if (blockIdx.x == 0) g_rr[b] = rr;
    }
    __syncthreads();
    float s = sh_s, th = sh_th, sc = sh_sc;
    const float4* dp4 = (const float4*)(g_dp  + (size_t)b * NPIX);
    const float4* dg4 = (const float4*)(g_dgt + (size_t)b * NPIX);
    const float4* pv4 = (const float4*)(prev + (size_t)b * NPIX);
    const unsigned char* mm = g_m12 + (size_t)b * NPIX4;
    float4* o4 = (float4*)(out + 4 + (size_t)b * NPIX);
    int lane = tid & 31;
    unsigned lmask = (1u << lane) - 1u;
    int tot_threads = gridDim.x * blockDim.x;
    for (int i = blockIdx.x * blockDim.x + tid; i < NPIX4; i += tot_threads) {
        float4 DP = dp4[i], DG = dg4[i], PV = pv4[i];
        unsigned mbyte = mm[i];
        float4 O;
        bool act[4]; float rdv[4], rav[4];
#define DO(c, idx) { float dp = s * DP.c; O.c = dp; \
        bool st = ((mbyte >> idx) & 1u) && (fabsf(DG.c) < th); \
        act[idx] = st; \
        rdv[idx] = fabsf(dp - DG.c) / sc; rav[idx] = fabsf(dp - PV.c) / sc; }
        DO(x, 0) DO(y, 1) DO(z, 2) DO(w, 3)
#undef DO
        unsigned bals[4]; int tot = 0;
#pragma unroll
        for (int q = 0; q < 4; q++) { bals[q] = __ballot_sync(0xffffffffu, act[q]); tot += __popc(bals[q]); }
        unsigned base = 0;
        if (lane == 0 && tot) base = (unsigned)atomicAdd(&g_cnt[b], tot);
        base = __shfl_sync(0xffffffffu, base, 0);
        unsigned off = base;
#pragma unroll
        for (int q = 0; q < 4; q++) {
            if (act[q]) {
                unsigned pos = off + __popc(bals[q] & lmask);
                g_rd_keys[(size_t)b * NPIX + pos] = fkey(rdv[q]);
                g_ra_keys[(size_t)b * NPIX + pos] = fkey(rav[q]);
            }
            off += __popc(bals[q]);
        }
        o4[i] = O;
    }
}

// Trimmed-huber: per (batch, j) block, 3-level smem radix select + huber sum.
__global__ void k_trim() {
    __shared__ unsigned int sh[2048];
    __shared__ unsigned int sP[257];
    __shared__ unsigned int s_prefix, s_rank;
    int tid = threadIdx.x;
    int b = blockIdx.y, j = blockIdx.x;
    const unsigned int* keys = (j ? g_ra_keys : g_rd_keys) + (size_t)b * NPIX;
    int cnt = g_cnt[b];
    int k = (int)floorf(0.6f * (float)cnt);
    if (k <= 0) { if (tid == 0) g_loss[b * 2 + j] = 0.f; return; }
    if (tid == 0) { s_rank = (unsigned)(k - 1); s_prefix = 0u; }
    __syncthreads();
    for (int level = 0; level < 3; level++) {
        int nb = (level == 2) ? 1024 : 2048;
        for (int i = tid; i < nb; i += 256) sh[i] = 0u;
        __syncthreads();
        unsigned pref = s_prefix;
        for (int i = tid; i < cnt; i += 256) {
            unsigned key = keys[i];
            if (level == 0) atomicAdd(&sh[key >> 21], 1u);
            else if (level == 1) { if ((key >> 21) == pref) atomicAdd(&sh[(key >> 10) & 2047u], 1u); }
            else                 { if ((key >> 10) == pref) atomicAdd(&sh[key & 1023u], 1u); }
        }
        __syncthreads();
        block_exscan_chunks(sh, sP, nb / 256);
        if (tid == 0) {
            unsigned bin, rem;
            resolve_one(sh, sP, nb / 256, nb, s_rank, &bin, &rem);
            s_rank = rem;
            s_prefix = pref * (unsigned)nb + bin;
        }
        __syncthreads();
    }
    unsigned target = s_prefix;
    float sum = 0.f;
    unsigned less = 0;
    for (int i = tid; i < cnt; i += 256) {
        unsigned key = keys[i];
        if (key < target) { sum += hubf(kinv(key)); less++; }
    }
    for (int o = 16; o > 0; o >>= 1) {
        sum  += __shfl_down_sync(0xffffffffu, sum, o);
        less += __shfl_down_sync(0xffffffffu, less, o);
    }
    __shared__ float ss[8];
    __shared__ unsigned sl[8];
    int lane = tid & 31, wp = tid >> 5;
    if (lane == 0) { ss[wp] = sum; sl[wp] = less; }
    __syncthreads();
    if (tid == 0) {
        float S = 0.f; unsigned L = 0;
        for (int w = 0; w < 8; w++) { S += ss[w]; L += sl[w]; }
        float ht = hubf(kinv(target));
        g_loss[b * 2 + j] = (S + (float)(k - (int)L) * ht) / (float)k;
    }
}

__global__ void k_final(float* __restrict__ out) {
    __shared__ float ld[BB], la[BB], rs[BB];
    int b = threadIdx.x;
    if (b < BB) { ld[b] = g_loss[b * 2]; la[b] = g_loss[b * 2 + 1]; rs[b] = g_rr[b]; }
    __syncthreads();
    if (threadIdx.x == 0) {
        float sld = 0.f, sla = 0.f, srr = 0.f;
        for (int i = 0; i < BB; i++) { sld += ld[i]; sla += la[i]; srr += rs[i]; }
        float loss_data = sld / (float)BB;
        float loss_acc  = sla / (float)BB;
        out[0] = loss_data + 0.2f * loss_acc;
        out[1] = loss_data;
        out[2] = loss_acc;
        out[3] = srr / (float)BB;
    }
}

extern "C" void kernel_launch(void* const* d_in, const int* in_sizes, int n_in,
                              void* d_out, int out_size) {
    const float* pred = (const float*)d_in[0];
    const float* gt   = (const float*)d_in[1];
    const float* mask = (const float*)d_in[2];
    const float* prev = (const float*)d_in[3];
    float* out = (float*)d_out;
    dim3 big(60, BB);

    k_zero<<<128, 256>>>();
    k_stats<<<big, 256>>>(pred, gt, mask);
    k_hist1<<<big, 256>>>();
    k_hist2<<<big, 256>>>();
    k_compact<<<big, 256>>>(prev, out);
    k_trim<<<dim3(2, BB), 256>>>();
    k_final<<<1, 32>>>(out);
}